// round 4
// baseline (speedup 1.0000x reference)
#include <cuda_runtime.h>
#include <cuda_bf16.h>
#include <math.h>

#define NN 50000          // nodes
#define NE 400000         // input edges
#define ET 450000         // edges + self loops
#define H0 8
#define C0 64
#define F0 128
#define FH 512            // H0*C0
#define NC 16

// ---------------- device scratch (no allocations allowed) ----------------
__device__ float g_bufA[NN * FH];      // linear GEMM output per layer
__device__ float g_bufB[NN * FH];      // aggregated+activated output
__device__ float g_bufC[NN * NC];      // layer-2 linear output
__device__ float g_als[NN * H0];
__device__ float g_ald[NN * H0];
__device__ float g_ex [ET * H0];       // per-(edge,head) alpha staging
__device__ int   g_deg[NN];
__device__ int   g_rowptr[NN + 1];
__device__ int   g_cursor[NN];
__device__ int   g_csr[ET];            // src node per CSR slot (sorted by dst)

__device__ __forceinline__ int clampi(int v) {
    return v < 0 ? 0 : (v >= NN ? NN - 1 : v);
}

// ---------------- CSR construction (edge_index is INT32: [2, NE]) ----------------
__global__ void k_zero_deg() {
    int i = blockIdx.x * blockDim.x + threadIdx.x;
    if (i < NN) g_deg[i] = 0;
}

__global__ void k_hist(const int* __restrict__ ei) {
    int e = blockIdx.x * blockDim.x + threadIdx.x;
    if (e >= ET) return;
    int d;
    if (e < NE) d = clampi(ei[NE + e]);
    else        d = e - NE;           // self loop
    atomicAdd(&g_deg[d], 1);
}

__global__ void k_scan() {           // single block, 1024 threads, exclusive scan
    __shared__ int s[1024];
    __shared__ int carry;
    int tid = threadIdx.x;
    if (tid == 0) carry = 0;
    __syncthreads();
    for (int base = 0; base < NN; base += 1024) {
        int i = base + tid;
        int v = (i < NN) ? g_deg[i] : 0;
        s[tid] = v;
        __syncthreads();
        for (int off = 1; off < 1024; off <<= 1) {
            int t = (tid >= off) ? s[tid - off] : 0;
            __syncthreads();
            s[tid] += t;
            __syncthreads();
        }
        if (i < NN) {
            int excl = carry + s[tid] - v;
            g_rowptr[i] = excl;
            g_cursor[i] = excl;
        }
        int tot = s[1023];
        __syncthreads();
        if (tid == 0) carry += tot;
        __syncthreads();
    }
    if (tid == 0) g_rowptr[NN] = ET;
}

__global__ void k_scatter(const int* __restrict__ ei) {
    int e = blockIdx.x * blockDim.x + threadIdx.x;
    if (e >= ET) return;
    int srcv, d;
    if (e < NE) { srcv = clampi(ei[e]); d = clampi(ei[NE + e]); }
    else        { srcv = e - NE;        d = e - NE; }
    int p = atomicAdd(&g_cursor[d], 1);
    if (p >= 0 && p < ET) g_csr[p] = srcv;
}

// ---------------- SGEMM: C = A(MxK) * B(KxN), row-major ----------------
// ASEL: -1 = use Aext param, 1 = g_bufB.  CSEL: 0 = g_bufA, 2 = g_bufC
#define BM 64
#define BN 64
#define BK 16
template <int ASEL, int CSEL>
__global__ void sgemm_kernel(const float* __restrict__ Aext, const float* __restrict__ B,
                             int M, int N, int K) {
    const float* __restrict__ A = (ASEL == 1) ? (const float*)g_bufB : Aext;
    float* __restrict__ C = (CSEL == 0) ? g_bufA : g_bufC;

    __shared__ float As[BK][BM];
    __shared__ float Bs[BK][BN];
    int tid = threadIdx.x;
    int tx = tid & 15, ty = tid >> 4;          // 16x16
    int row0 = blockIdx.y * BM;
    int col0 = blockIdx.x * BN;
    float acc[4][4];
#pragma unroll
    for (int i = 0; i < 4; i++)
#pragma unroll
        for (int j = 0; j < 4; j++) acc[i][j] = 0.f;

    for (int k0 = 0; k0 < K; k0 += BK) {
        for (int i = tid; i < BM * BK; i += 256) {
            int r = i / BK, c = i % BK;
            int gr = row0 + r;
            As[c][r] = (gr < M) ? A[(size_t)gr * K + k0 + c] : 0.f;
        }
        for (int i = tid; i < BK * BN; i += 256) {
            int r = i / BN, c = i % BN;
            int gc = col0 + c;
            Bs[r][c] = (gc < N) ? B[(size_t)(k0 + r) * N + gc] : 0.f;
        }
        __syncthreads();
#pragma unroll
        for (int kk = 0; kk < BK; kk++) {
            float a[4], b[4];
#pragma unroll
            for (int i = 0; i < 4; i++) a[i] = As[kk][ty * 4 + i];
#pragma unroll
            for (int j = 0; j < 4; j++) b[j] = Bs[kk][tx * 4 + j];
#pragma unroll
            for (int i = 0; i < 4; i++)
#pragma unroll
                for (int j = 0; j < 4; j++) acc[i][j] += a[i] * b[j];
        }
        __syncthreads();
    }
#pragma unroll
    for (int i = 0; i < 4; i++) {
        int row = row0 + ty * 4 + i;
        if (row >= M) continue;
#pragma unroll
        for (int j = 0; j < 4; j++) {
            int col = col0 + tx * 4 + j;
            if (col < N) C[(size_t)row * N + col] = acc[i][j];
        }
    }
}

// ---------------- attention dot products: als/ald per (node, head) ----------------
// HS: 0 = g_bufA, 2 = g_bufC
template <int H, int C, int HS>
__global__ void k_attdot(const float* __restrict__ a_s, const float* __restrict__ a_d) {
    const float* __restrict__ hin = (HS == 0) ? (const float*)g_bufA : (const float*)g_bufC;
    int warp = (blockIdx.x * blockDim.x + threadIdx.x) >> 5;
    int lane = threadIdx.x & 31;
    if (warp >= NN * H) return;
    int n = warp / H, h = warp - n * H;
    float s = 0.f, d = 0.f;
    for (int c = lane; c < C; c += 32) {
        float v = hin[(size_t)n * (H * C) + h * C + c];
        s += v * a_s[h * C + c];
        d += v * a_d[h * C + c];
    }
#pragma unroll
    for (int o = 16; o; o >>= 1) {
        s += __shfl_down_sync(0xffffffffu, s, o);
        d += __shfl_down_sync(0xffffffffu, d, o);
    }
    if (lane == 0) { g_als[n * H + h] = s; g_ald[n * H + h] = d; }
}

// ---------------- aggregation: softmax over incoming edges + weighted sum ----------------
// One block per destination node, blockDim = 32*H. Warp w owns head w.
// Per-head max/sum via warp shuffle butterflies only (no atomics).
// HS: 0 = g_bufA, 2 = g_bufC.  OS: 1 = g_bufB, -1 = use outext param
template <int H, int C, int DO_ELU, int HS, int OS>
__global__ void k_agg(const float* __restrict__ bias, float* __restrict__ outext) {
    constexpr int HC = H * C;
    const float* __restrict__ hin = (HS == 0) ? (const float*)g_bufA : (const float*)g_bufC;
    float* __restrict__ out = (OS == 1) ? g_bufB : outext;

    int n = blockIdx.x;
    int warp = threadIdx.x >> 5;            // == head
    int lane = threadIdx.x & 31;
    int beg = g_rowptr[n];
    int deg = g_rowptr[n + 1] - beg;

    __shared__ float sinv[H];

    {
        int h = warp;
        float ald_v = g_ald[n * H + h];
        // pass 1: max over incoming edges (deg >= 1 always: self-loop)
        float mx = -1e30f;
        for (int j = lane; j < deg; j += 32) {
            int src = g_csr[beg + j];
            float v = g_als[src * H + h] + ald_v;
            v = v > 0.f ? v : 0.2f * v;
            mx = fmaxf(mx, v);
        }
#pragma unroll
        for (int o = 16; o; o >>= 1) mx = fmaxf(mx, __shfl_xor_sync(0xffffffffu, mx, o));
        // pass 2: exp(v - max) -> stage, warp sum
        float sum = 0.f;
        for (int j = lane; j < deg; j += 32) {
            int src = g_csr[beg + j];
            float v = g_als[src * H + h] + ald_v;
            v = v > 0.f ? v : 0.2f * v;
            float ex = __expf(v - mx);
            g_ex[(beg + j) * H + h] = ex;
            sum += ex;
        }
#pragma unroll
        for (int o = 16; o; o >>= 1) sum += __shfl_xor_sync(0xffffffffu, sum, o);
        if (lane == 0) sinv[h] = 1.f / sum;
    }
    __syncthreads();

    // pass 3: out[n, o] = (sum_j ex_jh * hin[src_j, o]) * sinv[h] + bias[o] (+ ELU)
    for (int o = threadIdx.x; o < HC; o += 32 * H) {
        int h = o / C;
        float acc = 0.f;
        for (int j = 0; j < deg; j++) {
            int src = g_csr[beg + j];
            acc += g_ex[(beg + j) * H + h] * hin[(size_t)src * HC + o];
        }
        float r = acc * sinv[h] + bias[o];
        if (DO_ELU) r = r > 0.f ? r : expm1f(r);
        out[(size_t)n * HC + o] = r;
    }
}

// ---------------- launch (kernel launches ONLY — fully capture-safe) ----------------
extern "C" void kernel_launch(void* const* d_in, const int* in_sizes, int n_in,
                              void* d_out, int out_size) {
    const float* x   = (const float*)d_in[0];
    const int*   ei  = (const int*)d_in[1];       // int32 edge_index [2, NE]
    const float* W0  = (const float*)d_in[2];
    const float* as0 = (const float*)d_in[3];
    const float* ad0 = (const float*)d_in[4];
    const float* b0  = (const float*)d_in[5];
    const float* W1  = (const float*)d_in[6];
    const float* as1 = (const float*)d_in[7];
    const float* ad1 = (const float*)d_in[8];
    const float* b1  = (const float*)d_in[9];
    const float* W2  = (const float*)d_in[10];
    const float* as2 = (const float*)d_in[11];
    const float* ad2 = (const float*)d_in[12];
    const float* b2  = (const float*)d_in[13];
    float* out = (float*)d_out;

    // CSR build (per launch; deterministic)
    k_zero_deg<<<(NN + 255) / 256, 256>>>();
    k_hist<<<(ET + 255) / 256, 256>>>(ei);
    k_scan<<<1, 1024>>>();
    k_scatter<<<(ET + 255) / 256, 256>>>(ei);

    dim3 g0((FH + BN - 1) / BN, (NN + BM - 1) / BM);
    dim3 g2((NC + BN - 1) / BN, (NN + BM - 1) / BM);

    // layer 0: A = x (ext), C = g_bufA
    sgemm_kernel<-1, 0><<<g0, 256>>>(x, W0, NN, FH, F0);
    k_attdot<H0, C0, 0><<<(NN * H0 * 32 + 255) / 256, 256>>>(as0, ad0);
    k_agg<H0, C0, 1, 0, 1><<<NN, 32 * H0>>>(b0, nullptr);

    // layer 1: A = g_bufB, C = g_bufA
    sgemm_kernel<1, 0><<<g0, 256>>>(nullptr, W1, NN, FH, FH);
    k_attdot<H0, C0, 0><<<(NN * H0 * 32 + 255) / 256, 256>>>(as1, ad1);
    k_agg<H0, C0, 1, 0, 1><<<NN, 32 * H0>>>(b1, nullptr);

    // layer 2: A = g_bufB, C = g_bufC (H=1, C=16, no ELU, mean over 1 head == identity)
    sgemm_kernel<1, 2><<<g2, 256>>>(nullptr, W2, NN, NC, FH);
    k_attdot<1, NC, 2><<<(NN * 32 + 255) / 256, 256>>>(as2, ad2);
    k_agg<1, NC, 0, 2, -1><<<NN, 32>>>(b2, out);
}

// round 5
// speedup vs baseline: 1.3218x; 1.3218x over previous
#include <cuda_runtime.h>
#include <cuda_bf16.h>
#include <math.h>

#define NN 50000          // nodes
#define NE 400000         // input edges
#define ET 450000         // edges + self loops
#define H0 8
#define C0 64
#define F0 128
#define FH 512            // H0*C0
#define NC 16

// ---------------- device scratch (no allocations allowed) ----------------
__device__ float g_bufA[NN * FH];      // linear GEMM output per layer
__device__ float g_bufB[NN * FH];      // aggregated+activated output
__device__ float g_bufC[NN * NC];      // layer-2 linear output
__device__ float g_als[NN * H0];
__device__ float g_ald[NN * H0];
__device__ float g_ex [ET * H0];       // per-(edge,head) alpha staging
__device__ int   g_deg[NN];
__device__ int   g_rowptr[NN + 1];
__device__ int   g_cursor[NN];
__device__ int   g_csr[ET];            // src node per CSR slot (sorted by dst)

__device__ __forceinline__ int clampi(int v) {
    return v < 0 ? 0 : (v >= NN ? NN - 1 : v);
}

// ---------------- CSR construction (edge_index is INT32: [2, NE]) ----------------
__global__ void k_zero_deg() {
    int i = blockIdx.x * blockDim.x + threadIdx.x;
    if (i < NN) g_deg[i] = 0;
}

__global__ void k_hist(const int* __restrict__ ei) {
    int e = blockIdx.x * blockDim.x + threadIdx.x;
    if (e >= ET) return;
    int d;
    if (e < NE) d = clampi(ei[NE + e]);
    else        d = e - NE;           // self loop
    atomicAdd(&g_deg[d], 1);
}

__global__ void k_scan() {           // single block, 1024 threads, exclusive scan
    __shared__ int s[1024];
    __shared__ int carry;
    int tid = threadIdx.x;
    if (tid == 0) carry = 0;
    __syncthreads();
    for (int base = 0; base < NN; base += 1024) {
        int i = base + tid;
        int v = (i < NN) ? g_deg[i] : 0;
        s[tid] = v;
        __syncthreads();
        for (int off = 1; off < 1024; off <<= 1) {
            int t = (tid >= off) ? s[tid - off] : 0;
            __syncthreads();
            s[tid] += t;
            __syncthreads();
        }
        if (i < NN) {
            int excl = carry + s[tid] - v;
            g_rowptr[i] = excl;
            g_cursor[i] = excl;
        }
        int tot = s[1023];
        __syncthreads();
        if (tid == 0) carry += tot;
        __syncthreads();
    }
    if (tid == 0) g_rowptr[NN] = ET;
}

__global__ void k_scatter(const int* __restrict__ ei) {
    int e = blockIdx.x * blockDim.x + threadIdx.x;
    if (e >= ET) return;
    int srcv, d;
    if (e < NE) { srcv = clampi(ei[e]); d = clampi(ei[NE + e]); }
    else        { srcv = e - NE;        d = e - NE; }
    int p = atomicAdd(&g_cursor[d], 1);
    if (p >= 0 && p < ET) g_csr[p] = srcv;
}

// ================= big SGEMM: C = A(MxK)*B(KxN), 128x128x16 tile, double-buffered =====
// Requirements: K % 16 == 0, N % 128 == 0, pointers 16B-aligned.
// ASEL: -1 = use Aext param, 1 = g_bufB.  (C is always g_bufA)
#define TBM 128
#define TBN 128
#define TBK 16
template <int ASEL>
__global__ void __launch_bounds__(256, 2)
sgemm_big(const float* __restrict__ Aext, const float* __restrict__ B,
          int M, int N, int K) {
    const float* __restrict__ A = (ASEL == 1) ? (const float*)g_bufB : Aext;
    float* __restrict__ C = g_bufA;

    __shared__ float As[2][TBK][TBM];
    __shared__ float Bs[2][TBK][TBN];

    const int tid = threadIdx.x;
    const int row0 = blockIdx.y * TBM;
    const int col0 = blockIdx.x * TBN;

    // A-load mapping: 128 rows x 16 cols, float4 per load, 2 loads/thread
    const int ar = tid >> 2;           // 0..63
    const int ac = (tid & 3) * 4;      // 0,4,8,12
    // B-load mapping: 16 rows x 128 cols, float4 per load, 2 loads/thread
    const int br = tid >> 5;           // 0..7
    const int bc = (tid & 31) * 4;     // 0..124

    // compute mapping: 16x16 threads, 8x8 accumulators
    const int tx = tid & 15;
    const int ty = tid >> 4;

    const int gr0 = min(row0 + ar, M - 1);
    const int gr1 = min(row0 + ar + 64, M - 1);

    float acc[8][8];
#pragma unroll
    for (int i = 0; i < 8; i++)
#pragma unroll
        for (int j = 0; j < 8; j++) acc[i][j] = 0.f;

    const int ntiles = K / TBK;

    // preload tile 0 into buffer 0
    {
        float4 a0 = *(const float4*)&A[(size_t)gr0 * K + 0 + ac];
        float4 a1 = *(const float4*)&A[(size_t)gr1 * K + 0 + ac];
        float4 b0 = *(const float4*)&B[(size_t)(0 + br) * N + col0 + bc];
        float4 b1 = *(const float4*)&B[(size_t)(8 + br) * N + col0 + bc];
        As[0][ac + 0][ar] = a0.x; As[0][ac + 1][ar] = a0.y;
        As[0][ac + 2][ar] = a0.z; As[0][ac + 3][ar] = a0.w;
        As[0][ac + 0][ar + 64] = a1.x; As[0][ac + 1][ar + 64] = a1.y;
        As[0][ac + 2][ar + 64] = a1.z; As[0][ac + 3][ar + 64] = a1.w;
        *(float4*)&Bs[0][br][bc]     = b0;
        *(float4*)&Bs[0][br + 8][bc] = b1;
    }
    __syncthreads();

    for (int t = 0; t < ntiles; t++) {
        const int cur = t & 1;
        const int nxt = cur ^ 1;

        float4 a0, a1, b0, b1;
        const bool have_next = (t + 1 < ntiles);
        if (have_next) {
            const int k0 = (t + 1) * TBK;
            a0 = *(const float4*)&A[(size_t)gr0 * K + k0 + ac];
            a1 = *(const float4*)&A[(size_t)gr1 * K + k0 + ac];
            b0 = *(const float4*)&B[(size_t)(k0 + br) * N + col0 + bc];
            b1 = *(const float4*)&B[(size_t)(k0 + 8 + br) * N + col0 + bc];
        }

#pragma unroll
        for (int kk = 0; kk < TBK; kk++) {
            float4 aA = *(const float4*)&As[cur][kk][ty * 8];
            float4 aB = *(const float4*)&As[cur][kk][ty * 8 + 4];
            float4 bA = *(const float4*)&Bs[cur][kk][tx * 8];
            float4 bB = *(const float4*)&Bs[cur][kk][tx * 8 + 4];
            float a[8] = {aA.x, aA.y, aA.z, aA.w, aB.x, aB.y, aB.z, aB.w};
            float b[8] = {bA.x, bA.y, bA.z, bA.w, bB.x, bB.y, bB.z, bB.w};
#pragma unroll
            for (int i = 0; i < 8; i++)
#pragma unroll
                for (int j = 0; j < 8; j++) acc[i][j] += a[i] * b[j];
        }

        if (have_next) {
            As[nxt][ac + 0][ar] = a0.x; As[nxt][ac + 1][ar] = a0.y;
            As[nxt][ac + 2][ar] = a0.z; As[nxt][ac + 3][ar] = a0.w;
            As[nxt][ac + 0][ar + 64] = a1.x; As[nxt][ac + 1][ar + 64] = a1.y;
            As[nxt][ac + 2][ar + 64] = a1.z; As[nxt][ac + 3][ar + 64] = a1.w;
            *(float4*)&Bs[nxt][br][bc]     = b0;
            *(float4*)&Bs[nxt][br + 8][bc] = b1;
        }
        __syncthreads();
    }

    // store: rows guarded vs M, cols always valid (N % 128 == 0)
#pragma unroll
    for (int i = 0; i < 8; i++) {
        const int row = row0 + ty * 8 + i;
        if (row >= M) continue;
        float4 v0 = make_float4(acc[i][0], acc[i][1], acc[i][2], acc[i][3]);
        float4 v1 = make_float4(acc[i][4], acc[i][5], acc[i][6], acc[i][7]);
        *(float4*)&C[(size_t)row * N + col0 + tx * 8]     = v0;
        *(float4*)&C[(size_t)row * N + col0 + tx * 8 + 4] = v1;
    }
}

// ---------------- small SGEMM (layer 2, N=16): 64x64x16 tile ----------------
#define BM 64
#define BN 64
#define BK 16
__global__ void sgemm_small(const float* __restrict__ B, int M, int N, int K) {
    const float* __restrict__ A = g_bufB;
    float* __restrict__ C = g_bufC;

    __shared__ float As[BK][BM];
    __shared__ float Bs[BK][BN];
    int tid = threadIdx.x;
    int tx = tid & 15, ty = tid >> 4;
    int row0 = blockIdx.y * BM;
    int col0 = blockIdx.x * BN;
    float acc[4][4];
#pragma unroll
    for (int i = 0; i < 4; i++)
#pragma unroll
        for (int j = 0; j < 4; j++) acc[i][j] = 0.f;

    for (int k0 = 0; k0 < K; k0 += BK) {
        for (int i = tid; i < BM * BK; i += 256) {
            int r = i / BK, c = i % BK;
            int gr = row0 + r;
            As[c][r] = (gr < M) ? A[(size_t)gr * K + k0 + c] : 0.f;
        }
        for (int i = tid; i < BK * BN; i += 256) {
            int r = i / BN, c = i % BN;
            int gc = col0 + c;
            Bs[r][c] = (gc < N) ? B[(size_t)(k0 + r) * N + gc] : 0.f;
        }
        __syncthreads();
#pragma unroll
        for (int kk = 0; kk < BK; kk++) {
            float a[4], b[4];
#pragma unroll
            for (int i = 0; i < 4; i++) a[i] = As[kk][ty * 4 + i];
#pragma unroll
            for (int j = 0; j < 4; j++) b[j] = Bs[kk][tx * 4 + j];
#pragma unroll
            for (int i = 0; i < 4; i++)
#pragma unroll
                for (int j = 0; j < 4; j++) acc[i][j] += a[i] * b[j];
        }
        __syncthreads();
    }
#pragma unroll
    for (int i = 0; i < 4; i++) {
        int row = row0 + ty * 4 + i;
        if (row >= M) continue;
#pragma unroll
        for (int j = 0; j < 4; j++) {
            int col = col0 + tx * 4 + j;
            if (col < N) C[(size_t)row * N + col] = acc[i][j];
        }
    }
}

// ---------------- attention dot products: als/ald per (node, head) ----------------
// HS: 0 = g_bufA, 2 = g_bufC
template <int H, int C, int HS>
__global__ void k_attdot(const float* __restrict__ a_s, const float* __restrict__ a_d) {
    const float* __restrict__ hin = (HS == 0) ? (const float*)g_bufA : (const float*)g_bufC;
    int warp = (blockIdx.x * blockDim.x + threadIdx.x) >> 5;
    int lane = threadIdx.x & 31;
    if (warp >= NN * H) return;
    int n = warp / H, h = warp - n * H;
    float s = 0.f, d = 0.f;
    for (int c = lane; c < C; c += 32) {
        float v = hin[(size_t)n * (H * C) + h * C + c];
        s += v * a_s[h * C + c];
        d += v * a_d[h * C + c];
    }
#pragma unroll
    for (int o = 16; o; o >>= 1) {
        s += __shfl_down_sync(0xffffffffu, s, o);
        d += __shfl_down_sync(0xffffffffu, d, o);
    }
    if (lane == 0) { g_als[n * H + h] = s; g_ald[n * H + h] = d; }
}

// ---------------- aggregation: softmax over incoming edges + weighted sum ----------------
// One block per destination node, blockDim = 32*H. Warp w owns head w.
// HS: 0 = g_bufA, 2 = g_bufC.  OS: 1 = g_bufB, -1 = use outext param
template <int H, int C, int DO_ELU, int HS, int OS>
__global__ void k_agg(const float* __restrict__ bias, float* __restrict__ outext) {
    constexpr int HC = H * C;
    const float* __restrict__ hin = (HS == 0) ? (const float*)g_bufA : (const float*)g_bufC;
    float* __restrict__ out = (OS == 1) ? g_bufB : outext;

    int n = blockIdx.x;
    int warp = threadIdx.x >> 5;            // == head
    int lane = threadIdx.x & 31;
    int beg = g_rowptr[n];
    int deg = g_rowptr[n + 1] - beg;

    __shared__ float sinv[H];

    {
        int h = warp;
        float ald_v = g_ald[n * H + h];
        float mx = -1e30f;
        for (int j = lane; j < deg; j += 32) {
            int src = g_csr[beg + j];
            float v = g_als[src * H + h] + ald_v;
            v = v > 0.f ? v : 0.2f * v;
            mx = fmaxf(mx, v);
        }
#pragma unroll
        for (int o = 16; o; o >>= 1) mx = fmaxf(mx, __shfl_xor_sync(0xffffffffu, mx, o));
        float sum = 0.f;
        for (int j = lane; j < deg; j += 32) {
            int src = g_csr[beg + j];
            float v = g_als[src * H + h] + ald_v;
            v = v > 0.f ? v : 0.2f * v;
            float ex = __expf(v - mx);
            g_ex[(beg + j) * H + h] = ex;
            sum += ex;
        }
#pragma unroll
        for (int o = 16; o; o >>= 1) sum += __shfl_xor_sync(0xffffffffu, sum, o);
        if (lane == 0) sinv[h] = 1.f / sum;
    }
    __syncthreads();

    for (int o = threadIdx.x; o < HC; o += 32 * H) {
        int h = o / C;
        float acc = 0.f;
        for (int j = 0; j < deg; j++) {
            int src = g_csr[beg + j];
            acc += g_ex[(beg + j) * H + h] * hin[(size_t)src * HC + o];
        }
        float r = acc * sinv[h] + bias[o];
        if (DO_ELU) r = r > 0.f ? r : expm1f(r);
        out[(size_t)n * HC + o] = r;
    }
}

// ---------------- launch (kernel launches ONLY — fully capture-safe) ----------------
extern "C" void kernel_launch(void* const* d_in, const int* in_sizes, int n_in,
                              void* d_out, int out_size) {
    const float* x   = (const float*)d_in[0];
    const int*   ei  = (const int*)d_in[1];       // int32 edge_index [2, NE]
    const float* W0  = (const float*)d_in[2];
    const float* as0 = (const float*)d_in[3];
    const float* ad0 = (const float*)d_in[4];
    const float* b0  = (const float*)d_in[5];
    const float* W1  = (const float*)d_in[6];
    const float* as1 = (const float*)d_in[7];
    const float* ad1 = (const float*)d_in[8];
    const float* b1  = (const float*)d_in[9];
    const float* W2  = (const float*)d_in[10];
    const float* as2 = (const float*)d_in[11];
    const float* ad2 = (const float*)d_in[12];
    const float* b2  = (const float*)d_in[13];
    float* out = (float*)d_out;

    // CSR build (per launch; deterministic)
    k_zero_deg<<<(NN + 255) / 256, 256>>>();
    k_hist<<<(ET + 255) / 256, 256>>>(ei);
    k_scan<<<1, 1024>>>();
    k_scatter<<<(ET + 255) / 256, 256>>>(ei);

    dim3 gbig(FH / TBN, (NN + TBM - 1) / TBM);      // 4 x 391
    dim3 g2((NC + BN - 1) / BN, (NN + BM - 1) / BM);

    // layer 0: A = x (ext), C = g_bufA
    sgemm_big<-1><<<gbig, 256>>>(x, W0, NN, FH, F0);
    k_attdot<H0, C0, 0><<<(NN * H0 * 32 + 255) / 256, 256>>>(as0, ad0);
    k_agg<H0, C0, 1, 0, 1><<<NN, 32 * H0>>>(b0, nullptr);

    // layer 1: A = g_bufB, C = g_bufA
    sgemm_big<1><<<gbig, 256>>>(nullptr, W1, NN, FH, FH);
    k_attdot<H0, C0, 0><<<(NN * H0 * 32 + 255) / 256, 256>>>(as1, ad1);
    k_agg<H0, C0, 1, 0, 1><<<NN, 32 * H0>>>(b1, nullptr);

    // layer 2: A = g_bufB, C = g_bufC (H=1, C=16, no ELU)
    sgemm_small<<<g2, 256>>>(W2, NN, NC, FH);
    k_attdot<1, NC, 2><<<(NN * 32 + 255) / 256, 256>>>(as2, ad2);
    k_agg<1, NC, 0, 2, -1><<<NN, 32>>>(b2, out);
}